// round 16
// baseline (speedup 1.0000x reference)
#include <cuda_runtime.h>
#include <cuda_bf16.h>
#include <cuda_fp16.h>
#include <math.h>
#include <stdint.h>

// ---------------- problem constants ----------------
static const int B_   = 2;
static const int L_   = 2048;
static const int DM   = 256;
static const int DS   = 128;
static const int DI   = 1024;
static const int NH   = 16;
static const int HD   = 64;
static const int CD   = 1280;
static const int DIP  = 2320;
static const int CH   = 256;
static const int NC   = 8;
#define GN_EPS 1.1920928955078125e-07f
#define RMS_EPS 1e-5f

#define SZ_ZX   ((long long)B_*L_*DIP)
#define SZ_XBC  ((long long)B_*L_*CD)
#define SZ_DT   ((long long)B_*L_*NH)
#define SZ_ACS  ((long long)B_*NH*L_)
#define SZ_CB   ((long long)B_*NC*CH*CH)
#define SZ_ST   ((long long)B_*NC*NH*HD*DS)
#define SZ_Y    ((long long)B_*L_*DI)

#define CVT_TOTAL (2*DIP*DM + 2*DM*DI + DM*2*DM)
#define CVT_BLOCKS ((CVT_TOTAL + 255) / 256)
#define GNP_BLOCKS (64 * B_)
#define CONV_BLOCKS ((int)((2LL * B_ * (L_/4) * (CD/4) + 255) / 256))
#define DTS_BLOCKS (2 * B_ * NH * NC)

// ---------------- scratch ----------------
__device__ float  g_t    [B_*L_*DM];
__device__ __half g_th   [B_*L_*DM];
__device__ __half g_zx   [2*B_*L_*DIP];
__device__ __half g_xbc  [2*B_*L_*CD];
__device__ float  g_dt   [2*B_*L_*NH];
__device__ float  g_acs  [2*B_*NH*L_];
__device__ __half g_cb   [2*B_*NC*CH*CH];
__device__ float  g_st   [2*B_*NC*NH*HD*DS];
__device__ float  g_pv   [2*B_*NC*NH*HD*DS];
__device__ __half g_yh   [2*B_*L_*DI];
__device__ __half g_rh   [B_*L_*2*DM];
__device__ __half g_wih  [2*DIP*DM];
__device__ __half g_woh  [2*DM*DI];
__device__ __half g_wph  [DM*2*DM];
__device__ float  g_part [B_*64*2];
__device__ float  g_stats[4];

__device__ __forceinline__ float siluf(float x) { return x / (1.f + __expf(-x)); }
__device__ __forceinline__ float softplusf(float x) { return x > 20.f ? x : log1pf(expf(x)); }

#define MMA_F16(acc, a, b) \
    asm volatile( \
        "mma.sync.aligned.m16n8k16.row.col.f32.f16.f16.f32 " \
        "{%0,%1,%2,%3},{%4,%5,%6,%7},{%8,%9},{%0,%1,%2,%3};" \
        : "+f"((acc)[0]), "+f"((acc)[1]), "+f"((acc)[2]), "+f"((acc)[3]) \
        : "r"((a)[0]), "r"((a)[1]), "r"((a)[2]), "r"((a)[3]), \
          "r"((b)[0]), "r"((b)[1]))

__device__ __forceinline__ void cpa16(uint32_t dst, const void* src, bool valid) {
    int sz = valid ? 16 : 0;
    asm volatile("cp.async.cg.shared.global [%0], [%1], 16, %2;\n"
                 :: "r"(dst), "l"(src), "r"(sz));
}
#define CPA_COMMIT() asm volatile("cp.async.commit_group;\n" ::)
#define CPA_WAIT1()  asm volatile("cp.async.wait_group 1;\n" ::)

// ---------------- fused: weight conversion + GroupNorm partials -------------
__global__ void prep_k(const float* __restrict__ a0, const float* __restrict__ a1,
                       const float* __restrict__ a2, const float* __restrict__ a3,
                       const float* __restrict__ a4,
                       __half* __restrict__ w_in, __half* __restrict__ w_out,
                       __half* __restrict__ w_pj,
                       const float* __restrict__ x, float* __restrict__ part) {
    int bi = blockIdx.x;
    if (bi < CVT_BLOCKS) {
        const int N1 = DIP * DM, N2 = DM * DI, N3 = DM * 2 * DM;
        int i = bi * 256 + threadIdx.x;
        if (i < N1) w_in[i] = __float2half(a0[i]);
        else if (i < 2 * N1) w_in[i] = __float2half(a1[i - N1]);
        else {
            int j = i - 2 * N1;
            if (j < N2) w_out[j] = __float2half(a2[j]);
            else if (j < 2 * N2) w_out[j] = __float2half(a3[j - N2]);
            else { int k = j - 2 * N2; if (k < N3) w_pj[k] = __float2half(a4[k]); }
        }
        return;
    }
    int gi = bi - CVT_BLOCKS;
    int b = gi / 64, blk = gi % 64;
    const float* xb = x + (size_t)b * DM * L_;
    float s = 0.f, ss = 0.f;
    for (int i = blk * 256 + threadIdx.x; i < DM * L_; i += 64 * 256) {
        float v = xb[i]; s += v; ss += v * v;
    }
    __shared__ float sh[256], sh2[256];
    sh[threadIdx.x] = s; sh2[threadIdx.x] = ss;
    __syncthreads();
    for (int o = 128; o > 0; o >>= 1) {
        if ((int)threadIdx.x < o) { sh[threadIdx.x] += sh[threadIdx.x + o]; sh2[threadIdx.x] += sh2[threadIdx.x + o]; }
        __syncthreads();
    }
    if (threadIdx.x == 0) {
        part[(b * 64 + blk) * 2 + 0] = sh[0];
        part[(b * 64 + blk) * 2 + 1] = sh2[0];
    }
}

__global__ void gn_fin_k(const float* __restrict__ part, float* __restrict__ stats) {
    int b = blockIdx.x;
    __shared__ double sh[64], sh2[64];
    int i = threadIdx.x;
    sh[i]  = (double)part[(b * 64 + i) * 2 + 0];
    sh2[i] = (double)part[(b * 64 + i) * 2 + 1];
    __syncthreads();
    for (int o = 32; o > 0; o >>= 1) {
        if (i < o) { sh[i] += sh[i + o]; sh2[i] += sh2[i + o]; }
        __syncthreads();
    }
    if (i == 0) {
        double n = (double)DM * L_;
        double mu = sh[0] / n;
        double var = sh2[0] / n - mu * mu;
        stats[b * 2 + 0] = (float)mu;
        stats[b * 2 + 1] = rsqrtf((float)var + GN_EPS);
    }
}

// ---------------- GroupNorm apply + transpose ----------------
__global__ void gn_apply_k(const float* __restrict__ x, const float* __restrict__ gw,
                           const float* __restrict__ gb, const float* __restrict__ stats,
                           float* __restrict__ t, __half* __restrict__ th) {
    int b = blockIdx.z;
    __shared__ float tile[32][33];
    int l0 = blockIdx.x * 32, d0 = blockIdx.y * 32;
    float mu = stats[b * 2], rs = stats[b * 2 + 1];
#pragma unroll
    for (int r = 0; r < 4; r++) {
        int d = d0 + threadIdx.y + r * 8;
        tile[threadIdx.y + r * 8][threadIdx.x] = x[((size_t)b * DM + d) * L_ + l0 + threadIdx.x];
    }
    __syncthreads();
    int d = d0 + threadIdx.x;
    float w = gw[d], bb = gb[d];
#pragma unroll
    for (int r = 0; r < 4; r++) {
        int l = l0 + threadIdx.y + r * 8;
        float v = (tile[threadIdx.x][threadIdx.y + r * 8] - mu) * rs * w + bb;
        t[((size_t)b * L_ + l) * DM + d] = v;
        th[((size_t)b * L_ + l) * DM + d] = __float2half(v);
    }
}

// ---- FP16 NT GEMM, two tile configs ----------------------------------------
// TB=1: 128x128 tile, 8 warps 4x2 (32x64 each)  — big GEMMs
// TB=0:  64x64  tile, 8 warps 2x4 (32x16 each)  — small GEMMs (chip fill)
#define HBK 64
#define GST 3
#define GLDH2 72
#define H_SMEM_BIG   (GST * 256 * GLDH2 * 2)
#define H_SMEM_SMALL (GST * 128 * GLDH2 * 2)

template<int MODE, int TB>
__global__ void __launch_bounds__(256, (TB ? 2 : 3))
gemm_h(const __half* __restrict__ A, const __half* __restrict__ B0,
       const __half* __restrict__ B1, void* __restrict__ Cv,
       int M, int N, int K, int lda, int ldb, int ldc,
       long long sA, long long sB, long long sC,
       int zPerDir, long long dA, long long dC, int revL,
       const float* __restrict__ extra, const float* __restrict__ bias) {
    constexpr int T   = 256;
    constexpr int BMx = TB ? 128 : 64;
    constexpr int BNx = TB ? 128 : 64;
    constexpr int MF  = 2;
    constexpr int NF  = TB ? 8 : 2;
    constexpr int WTN = NF * 8;           // warp tile N
    constexpr int WNW = BNx / WTN;        // warps in N (2 or 4)
    constexpr int LA  = BMx * HBK / (T * 8);
    constexpr int LB  = BNx * HBK / (T * 8);
    extern __shared__ __half hsm[];
    __half* Asm = hsm;
    __half* Bsm = hsm + GST * BMx * GLDH2;
    int z = blockIdx.z;
    int dir = z / zPerDir, zz = z % zPerDir;
    const __half* Ap = A + dir * dA + zz * sA;
    const __half* Bp = (dir ? B1 : B0) + zz * sB;
    long long coff = dir * dC + zz * sC;
    int rev = dir ? revL : 0;
    int m0 = blockIdx.y * BMx, n0 = blockIdx.x * BNx;
    int tid = threadIdx.x;
    int warp = tid >> 5, lane = tid & 31;
    int wm = warp / WNW, wn = warp % WNW;
    int group = lane >> 2, tig = lane & 3;
    float acc[MF][NF][4] = {};

    auto issue = [&](int k0, int s) {
        __half* As = Asm + s * BMx * GLDH2;
        __half* Bs = Bsm + s * BNx * GLDH2;
#pragma unroll
        for (int i = 0; i < LA; i++) {
            int e = tid + i * T;
            int mm = e >> 3;
            int kc = (e & 7) * 8;
            int gm = m0 + mm;
            int row = gm < M ? gm : 0;
            if (rev && gm < M) { int bb = gm / rev; int ll = gm % rev; row = bb * rev + (rev - 1 - ll); }
            cpa16((uint32_t)__cvta_generic_to_shared(As + mm * GLDH2 + kc),
                  Ap + (long long)row * lda + k0 + kc, gm < M);
        }
#pragma unroll
        for (int i = 0; i < LB; i++) {
            int e = tid + i * T;
            int nn = e >> 3;
            int kc = (e & 7) * 8;
            int gn = n0 + nn;
            int rowb = gn < N ? gn : 0;
            cpa16((uint32_t)__cvta_generic_to_shared(Bs + nn * GLDH2 + kc),
                  Bp + (long long)rowb * ldb + k0 + kc, gn < N);
        }
    };
    auto compute = [&](int s) {
        const __half2* As2 = reinterpret_cast<const __half2*>(Asm + s * BMx * GLDH2);
        const __half2* Bs2 = reinterpret_cast<const __half2*>(Bsm + s * BNx * GLDH2);
#pragma unroll
        for (int ks = 0; ks < 4; ks++) {
            int k2 = ks * 8;
            uint32_t af[MF][4], bf[NF][2];
#pragma unroll
            for (int mf = 0; mf < MF; mf++) {
                int rm = wm * 32 + mf * 16 + group;
                af[mf][0] = *reinterpret_cast<const uint32_t*>(&As2[(rm    ) * 36 + k2 + tig]);
                af[mf][1] = *reinterpret_cast<const uint32_t*>(&As2[(rm + 8) * 36 + k2 + tig]);
                af[mf][2] = *reinterpret_cast<const uint32_t*>(&As2[(rm    ) * 36 + k2 + tig + 4]);
                af[mf][3] = *reinterpret_cast<const uint32_t*>(&As2[(rm + 8) * 36 + k2 + tig + 4]);
            }
#pragma unroll
            for (int nf = 0; nf < NF; nf++) {
                int rn = wn * WTN + nf * 8 + group;
                bf[nf][0] = *reinterpret_cast<const uint32_t*>(&Bs2[rn * 36 + k2 + tig]);
                bf[nf][1] = *reinterpret_cast<const uint32_t*>(&Bs2[rn * 36 + k2 + tig + 4]);
            }
#pragma unroll
            for (int mf = 0; mf < MF; mf++)
#pragma unroll
                for (int nf = 0; nf < NF; nf++) MMA_F16(acc[mf][nf], af[mf], bf[nf]);
        }
    };

    int nIter = K / HBK;
    issue(0, 0);
    CPA_COMMIT();
    if (nIter > 1) issue(HBK, 1);
    CPA_COMMIT();
    for (int it = 0; it < nIter; it++) {
        CPA_WAIT1();
        __syncthreads();
        if (it + 2 < nIter) issue((it + 2) * HBK, (it + 2) % GST);
        CPA_COMMIT();
        compute(it % GST);
    }

#pragma unroll
    for (int mf = 0; mf < MF; mf++) {
#pragma unroll
        for (int nf = 0; nf < NF; nf++) {
            int gn = n0 + wn * WTN + nf * 8 + 2 * tig;
#pragma unroll
            for (int rr = 0; rr < 2; rr++) {
                int gm = m0 + wm * 32 + mf * 16 + group + rr * 8;
                float a0 = acc[mf][nf][rr * 2 + 0], a1 = acc[mf][nf][rr * 2 + 1];
                if (MODE == 0) {
                    if (gm < M && gn < N) {
                        __half2* cp2 = reinterpret_cast<__half2*>(Cv);
                        cp2[(coff + (long long)gm * ldc + gn) >> 1] = __floats2half2_rn(a0, a1);
                    }
                } else if (MODE == 1) {
                    int b = gm / L_, l = gm % L_;
                    int ltm = dir ? (L_ - 1 - l) : l;
                    long long base = (long long)(b * L_ + ltm);
                    float2 tv = *reinterpret_cast<const float2*>(extra + base * DM + gn);
                    __half2* rp = reinterpret_cast<__half2*>(Cv);
                    rp[(base * (2 * DM) + dir * DM + gn) >> 1] =
                        __floats2half2_rn(a0 + tv.x, a1 + tv.y);
                } else {
                    int b = gm / L_, l = gm % L_;
                    float* C = reinterpret_cast<float*>(Cv);
                    long long i0 = ((long long)(b * DM + gn)) * L_ + l;
                    long long i1 = ((long long)(b * DM + gn + 1)) * L_ + l;
                    C[i0] = extra[i0] + bias[gn] + a0;
                    C[i1] = extra[i1] + bias[gn + 1] + a1;
                }
            }
        }
    }
}

// ---------------- fused: depthwise conv+SiLU  AND  dt softplus+scan ---------
__global__ void convdt_k(const __half* __restrict__ zx,
                         const float* __restrict__ cw0, const float* __restrict__ cb0,
                         const float* __restrict__ cw1, const float* __restrict__ cb1,
                         const float* __restrict__ db0, const float* __restrict__ al0,
                         const float* __restrict__ db1, const float* __restrict__ al1,
                         __half* __restrict__ xbc,
                         float* __restrict__ dt, float* __restrict__ acs) {
    int bi = blockIdx.x;
    if (bi < CONV_BLOCKS) {
        long long idx = (long long)bi * 256 + threadIdx.x;
        if (idx >= 2LL * B_ * (L_ / 4) * (CD / 4)) return;
        int cg = idx % (CD / 4);
        int lb = (idx / (CD / 4)) % (L_ / 4);
        long long rest = idx / ((long long)(CD / 4) * (L_ / 4));
        int b = rest % B_;
        int dir = rest / B_;
        int l0 = lb * 4;
        const float* cw = (dir ? cw1 : cw0) + cg * 16;
        const float* cb = (dir ? cb1 : cb0) + cg * 4;
        const __half* zxd = zx + dir * SZ_ZX + (size_t)(b * L_) * DIP + DI + cg * 4;
        float4 w0 = *reinterpret_cast<const float4*>(cw);
        float4 w1 = *reinterpret_cast<const float4*>(cw + 4);
        float4 w2 = *reinterpret_cast<const float4*>(cw + 8);
        float4 w3 = *reinterpret_cast<const float4*>(cw + 12);
        float4 bv = *reinterpret_cast<const float4*>(cb);
        float4 v[7];
#pragma unroll
        for (int r = 0; r < 7; r++) {
            int lp = l0 - 3 + r;
            if (lp >= 0) {
                const __half2* p = reinterpret_cast<const __half2*>(zxd + (size_t)lp * DIP);
                float2 f0 = __half22float2(p[0]);
                float2 f1 = __half22float2(p[1]);
                v[r] = make_float4(f0.x, f0.y, f1.x, f1.y);
            } else v[r] = make_float4(0.f, 0.f, 0.f, 0.f);
        }
        __half* outp = xbc + dir * SZ_XBC + ((size_t)(b * L_ + l0)) * CD + cg * 4;
#pragma unroll
        for (int j = 0; j < 4; j++) {
            float4 acc = bv;
#pragma unroll
            for (int k = 0; k < 4; k++) {
                float4 f = v[j + k];
                acc.x += ((const float*)&w0)[k] * f.x;
                acc.y += ((const float*)&w1)[k] * f.y;
                acc.z += ((const float*)&w2)[k] * f.z;
                acc.w += ((const float*)&w3)[k] * f.w;
            }
            __half2* op = reinterpret_cast<__half2*>(outp + (size_t)j * CD);
            op[0] = __floats2half2_rn(siluf(acc.x), siluf(acc.y));
            op[1] = __floats2half2_rn(siluf(acc.z), siluf(acc.w));
        }
        return;
    }
    int di = bi - CONV_BLOCKS;
    int dir = di / (B_ * NH * NC);
    di %= B_ * NH * NC;
    int c = di % NC, h = (di / NC) % NH, b = di / (NC * NH);
    const float* dt_bias = dir ? db1 : db0;
    const float* A_log   = dir ? al1 : al0;
    int l = threadIdx.x;
    int lane = l & 31, warp = l >> 5;
    int gl = c * CH + l;
    int row = b * L_ + gl;
    float v = __half2float(zx[dir * SZ_ZX + (size_t)row * DIP + (DIP - NH) + h]) + dt_bias[h];
    float dtv = softplusf(v);
    dt[dir * SZ_DT + (size_t)row * NH + h] = dtv;
    float a = -expf(A_log[h]) * dtv;
#pragma unroll
    for (int o = 1; o < 32; o <<= 1) {
        float t = __shfl_up_sync(0xffffffff, a, o);
        if (lane >= o) a += t;
    }
    __shared__ float wsum[8];
    if (lane == 31) wsum[warp] = a;
    __syncthreads();
    float off = 0.f;
#pragma unroll
    for (int w = 0; w < 8; w++) if (w < warp) off += wsum[w];
    acs[dir * SZ_ACS + (size_t)(b * NH + h) * L_ + gl] = a + off;
}

// ---------------- per-chunk end state via fp16 mma ----------------
#define SLDH 40
__global__ void __launch_bounds__(256)
states_mma_k(const __half* __restrict__ xbc, const float* __restrict__ dt,
             const float* __restrict__ acs, float* __restrict__ st) {
    int h = blockIdx.x, c = blockIdx.y;
    int dir = blockIdx.z / B_, b = blockIdx.z % B_;
    const __half* xbcd = xbc + dir * SZ_XBC;
    const float* dtd  = dt  + dir * SZ_DT;
    const float* acsd = acs + dir * SZ_ACS;
    int tid = threadIdx.x;
    int warp = tid >> 5, lane = tid & 31;
    int wm = warp >> 2, wn = warp & 3;
    int group = lane >> 2, tig = lane & 3;
    __shared__ __half Xs[64][SLDH];
    __shared__ __half Bs[128][SLDH];
    __shared__ float wrow[CH];
    int acsbase = (b * NH + h) * L_ + c * CH;
    float csLast = acsd[acsbase + CH - 1];
    {
        int row = b * L_ + c * CH + tid;
        wrow[tid] = dtd[(size_t)row * NH + h] * __expf(csLast - acsd[acsbase + tid]);
    }
    __syncthreads();
    float acc[2][4][4] = {};
    for (int s0 = 0; s0 < CH; s0 += 32) {
#pragma unroll
        for (int i = 0; i < 8; i++) {
            int e = tid + i * 256;
            int pp = e & 63, ss = e >> 6;
            int row = b * L_ + c * CH + s0 + ss;
            Xs[pp][ss] = __float2half(
                __half2float(xbcd[(size_t)row * CD + h * HD + pp]) * wrow[s0 + ss]);
        }
#pragma unroll
        for (int i = 0; i < 16; i++) {
            int e = tid + i * 256;
            int nn = e & 127, ss = e >> 7;
            int row = b * L_ + c * CH + s0 + ss;
            Bs[nn][ss] = xbcd[(size_t)row * CD + DI + nn];
        }
        __syncthreads();
        const __half2* Xs2 = reinterpret_cast<const __half2*>(&Xs[0][0]);
        const __half2* Bs2 = reinterpret_cast<const __half2*>(&Bs[0][0]);
#pragma unroll
        for (int ks = 0; ks < 2; ks++) {
            int k2 = ks * 8;
            uint32_t af[2][4], bf[4][2];
#pragma unroll
            for (int mf = 0; mf < 2; mf++) {
                int rm = wm * 32 + mf * 16 + group;
                af[mf][0] = *reinterpret_cast<const uint32_t*>(&Xs2[(rm    ) * 20 + k2 + tig]);
                af[mf][1] = *reinterpret_cast<const uint32_t*>(&Xs2[(rm + 8) * 20 + k2 + tig]);
                af[mf][2] = *reinterpret_cast<const uint32_t*>(&Xs2[(rm    ) * 20 + k2 + tig + 4]);
                af[mf][3] = *reinterpret_cast<const uint32_t*>(&Xs2[(rm + 8) * 20 + k2 + tig + 4]);
            }
#pragma unroll
            for (int nf = 0; nf < 4; nf++) {
                int rn = wn * 32 + nf * 8 + group;
                bf[nf][0] = *reinterpret_cast<const uint32_t*>(&Bs2[rn * 20 + k2 + tig]);
                bf[nf][1] = *reinterpret_cast<const uint32_t*>(&Bs2[rn * 20 + k2 + tig + 4]);
            }
#pragma unroll
            for (int mf = 0; mf < 2; mf++)
#pragma unroll
                for (int nf = 0; nf < 4; nf++) MMA_F16(acc[mf][nf], af[mf], bf[nf]);
        }
        __syncthreads();
    }
    float* base = st + dir * SZ_ST + (size_t)((b * NC + c) * NH + h) * HD * DS;
#pragma unroll
    for (int mf = 0; mf < 2; mf++) {
#pragma unroll
        for (int nf = 0; nf < 4; nf++) {
            int gm = wm * 32 + mf * 16 + group;
            int gn = wn * 32 + nf * 8 + 2 * tig;
            *reinterpret_cast<float2*>(base + gm * DS + gn) =
                make_float2(acc[mf][nf][0], acc[mf][nf][1]);
            *reinterpret_cast<float2*>(base + (gm + 8) * DS + gn) =
                make_float2(acc[mf][nf][2], acc[mf][nf][3]);
        }
    }
}

// ---------------- inter-chunk recurrence ----------------
__global__ void chunkscan_k(const float* __restrict__ st, const float* __restrict__ acs,
                            float* __restrict__ pv) {
    int idx = blockIdx.x * blockDim.x + threadIdx.x;
    int n = idx & (DS - 1);
    int p = (idx >> 7) & (HD - 1);
    int h = (idx >> 13) & (NH - 1);
    int b = (idx >> 17) & (B_ - 1);
    int dir = idx >> 18;
    const float* std_ = st + dir * SZ_ST;
    const float* acsd = acs + dir * SZ_ACS;
    float* pvd = pv + dir * SZ_ST;
    float S = 0.f;
    for (int c = 0; c < NC; c++) {
        size_t off = ((size_t)((b * NC + c) * NH + h) * HD + p) * DS + n;
        pvd[off] = S;
        float at = acsd[(b * NH + h) * L_ + c * CH + CH - 1];
        S = S * expf(at) + std_[off];
    }
}

// ---------------- Y via fp16 mma -> fp16 output ----------------
__global__ void __launch_bounds__(256)
ssd_y_mma_k(const __half* __restrict__ xbc, const float* __restrict__ dt,
            const float* __restrict__ acs, const __half* __restrict__ cb,
            const float* __restrict__ pv,
            const float* __restrict__ Dh0, const float* __restrict__ Dh1,
            __half* __restrict__ yh) {
    int lt = blockIdx.x, h = blockIdx.y;
    int dir = blockIdx.z / (B_ * NC);
    int bc = blockIdx.z % (B_ * NC);
    int c = bc % NC, b = bc / NC;
    const __half* xbcd = xbc + dir * SZ_XBC;
    const float* dtd  = dt  + dir * SZ_DT;
    const float* acsd = acs + dir * SZ_ACS;
    const float* Dh   = dir ? Dh1 : Dh0;
    int tid = threadIdx.x;
    int warp = tid >> 5, lane = tid & 31;
    int wm = warp >> 2, wn = warp & 3;
    int group = lane >> 2, tig = lane & 3;
    __shared__ __half Ws[64][SLDH];
    __shared__ __half Xs[64][SLDH];
    __shared__ __half Ps[64][SLDH];
    __shared__ float csl[64], el64[64], eoff[64];
    __shared__ float einv[CH];
    int l0 = lt * 64;
    int acsbase = (b * NH + h) * L_ + c * CH;
    float csl0 = acsd[acsbase + l0];
    if (tid < 64) {
        float v = acsd[acsbase + l0 + tid];
        csl[tid]  = v;
        el64[tid] = __expf(v - csl0);
        eoff[tid] = __expf(v);
    }
    einv[tid] = __expf(csl0 - acsd[acsbase + tid]);
    __syncthreads();
    const __half* cbb = cb + dir * SZ_CB + (size_t)(b * NC + c) * CH * CH;
    float acc[2][2][4] = {};
    int nst = 2 * lt + 2;
    for (int stp = 0; stp < nst; stp++) {
        int s0 = stp * 32;
        bool lower = (s0 + 31 < l0);
        if (lower) {
#pragma unroll
            for (int i = 0; i < 8; i++) {
                int e = tid + i * 256;
                int j = e & 31, ii = e >> 5;
                Ws[ii][j] = __float2half(el64[ii] * einv[s0 + j] *
                                         __half2float(cbb[(l0 + ii) * CH + s0 + j]));
            }
        } else {
#pragma unroll
            for (int i = 0; i < 8; i++) {
                int e = tid + i * 256;
                int j = e & 31, ii = e >> 5;
                float w = 0.f;
                if (s0 + j <= l0 + ii)
                    w = __expf(csl[ii] - acsd[acsbase + s0 + j]) *
                        __half2float(cbb[(l0 + ii) * CH + s0 + j]);
                Ws[ii][j] = __float2half(w);
            }
        }
#pragma unroll
        for (int i = 0; i < 8; i++) {
            int e = tid + i * 256;
            int pp = e & 63, ss = e >> 6;
            int row = b * L_ + c * CH + s0 + ss;
            Xs[pp][ss] = __float2half(
                __half2float(xbcd[(size_t)row * CD + h * HD + pp]) * dtd[(size_t)row * NH + h]);
        }
        __syncthreads();
        const __half2* Ws2 = reinterpret_cast<const __half2*>(&Ws[0][0]);
        const __half2* Xs2 = reinterpret_cast<const __half2*>(&Xs[0][0]);
#pragma unroll
        for (int ks = 0; ks < 2; ks++) {
            int k2 = ks * 8;
            uint32_t af[2][4], bf[2][2];
#pragma unroll
            for (int mf = 0; mf < 2; mf++) {
                int rm = wm * 32 + mf * 16 + group;
                af[mf][0] = *reinterpret_cast<const uint32_t*>(&Ws2[(rm    ) * 20 + k2 + tig]);
                af[mf][1] = *reinterpret_cast<const uint32_t*>(&Ws2[(rm + 8) * 20 + k2 + tig]);
                af[mf][2] = *reinterpret_cast<const uint32_t*>(&Ws2[(rm    ) * 20 + k2 + tig + 4]);
                af[mf][3] = *reinterpret_cast<const uint32_t*>(&Ws2[(rm + 8) * 20 + k2 + tig + 4]);
            }
#pragma unroll
            for (int nf = 0; nf < 2; nf++) {
                int rn = wn * 16 + nf * 8 + group;
                bf[nf][0] = *reinterpret_cast<const uint32_t*>(&Xs2[rn * 20 + k2 + tig]);
                bf[nf][1] = *reinterpret_cast<const uint32_t*>(&Xs2[rn * 20 + k2 + tig + 4]);
            }
#pragma unroll
            for (int mf = 0; mf < 2; mf++)
#pragma unroll
                for (int nf = 0; nf < 2; nf++) MMA_F16(acc[mf][nf], af[mf], bf[nf]);
        }
        __syncthreads();
    }
    const float* pvb = pv + dir * SZ_ST + (size_t)((b * NC + c) * NH + h) * HD * DS;
    for (int nt = 0; nt < 4; nt++) {
        int n0 = nt * 32;
#pragma unroll
        for (int i = 0; i < 8; i++) {
            int e = tid + i * 256;
            int j = e & 31, ii = e >> 5;
            int row = b * L_ + c * CH + l0 + ii;
            Ws[ii][j] = __float2half(
                __half2float(xbcd[(size_t)row * CD + DI + DS + n0 + j]) * eoff[ii]);
        }
#pragma unroll
        for (int i = 0; i < 8; i++) {
            int e = tid + i * 256;
            int j = e & 31, pp = e >> 5;
            Ps[pp][j] = __float2half(pvb[pp * DS + n0 + j]);
        }
        __syncthreads();
        const __half2* Ws2 = reinterpret_cast<const __half2*>(&Ws[0][0]);
        const __half2* Ps2 = reinterpret_cast<const __half2*>(&Ps[0][0]);
#pragma unroll
        for (int ks = 0; ks < 2; ks++) {
            int k2 = ks * 8;
            uint32_t af[2][4], bf[2][2];
#pragma unroll
            for (int mf = 0; mf < 2; mf++) {
                int rm = wm * 32 + mf * 16 + group;
                af[mf][0] = *reinterpret_cast<const uint32_t*>(&Ws2[(rm    ) * 20 + k2 + tig]);
                af[mf][1] = *reinterpret_cast<const uint32_t*>(&Ws2[(rm + 8) * 20 + k2 + tig]);
                af[mf][2] = *reinterpret_cast<const uint32_t*>(&Ws2[(rm    ) * 20 + k2 + tig + 4]);
                af[mf][3] = *reinterpret_cast<const uint32_t*>(&Ws2[(rm + 8) * 20 + k2 + tig + 4]);
            }
#pragma unroll
            for (int nf = 0; nf < 2; nf++) {
                int rn = wn * 16 + nf * 8 + group;
                bf[nf][0] = *reinterpret_cast<const uint32_t*>(&Ps2[rn * 20 + k2 + tig]);
                bf[nf][1] = *reinterpret_cast<const uint32_t*>(&Ps2[rn * 20 + k2 + tig + 4]);
            }
#pragma unroll
            for (int mf = 0; mf < 2; mf++)
#pragma unroll
                for (int nf = 0; nf < 2; nf++) MMA_F16(acc[mf][nf], af[mf], bf[nf]);
        }
        __syncthreads();
    }
    float dh = Dh[h];
    __half* yd = yh + dir * SZ_Y;
#pragma unroll
    for (int mf = 0; mf < 2; mf++) {
#pragma unroll
        for (int nf = 0; nf < 2; nf++) {
            int ll = l0 + wm * 32 + mf * 16 + group;
            int pp = wn * 16 + nf * 8 + 2 * tig;
#pragma unroll
            for (int rr = 0; rr < 2; rr++) {
                int row = b * L_ + c * CH + ll + rr * 8;
                __half2 xrh = *reinterpret_cast<const __half2*>(
                    xbcd + (size_t)row * CD + h * HD + pp);
                float2 xr = __half22float2(xrh);
                *reinterpret_cast<__half2*>(yd + (size_t)row * DI + h * HD + pp) =
                    __floats2half2_rn(acc[mf][nf][rr * 2 + 0] + xr.x * dh,
                                      acc[mf][nf][rr * 2 + 1] + xr.y * dh);
            }
        }
    }
}

// ---------------- gating + RMSNorm, in place on fp16 yh ----------------
__global__ void gate_rms_k(__half* __restrict__ yh, const __half* __restrict__ zx,
                           const float* __restrict__ nw0, const float* __restrict__ nw1) {
    int row = blockIdx.x;
    int dir = row / (B_ * L_);
    row %= B_ * L_;
    const float* nw = dir ? nw1 : nw0;
    __half* yd = yh + dir * SZ_Y + (size_t)row * DI;
    const __half* zxd = zx + dir * SZ_ZX + (size_t)row * DIP;
    int tid = threadIdx.x;
    const __half2* yp = reinterpret_cast<const __half2*>(yd) + tid * 2;
    float2 y0 = __half22float2(yp[0]);
    float2 y1 = __half22float2(yp[1]);
    const __half2* zp = reinterpret_cast<const __half2*>(zxd + tid * 4);
    float2 z0 = __half22float2(zp[0]);
    float2 z1 = __half22float2(zp[1]);
    y0.x *= siluf(z0.x); y0.y *= siluf(z0.y); y1.x *= siluf(z1.x); y1.y *= siluf(z1.y);
    float ss = y0.x * y0.x + y0.y * y0.y + y1.x * y1.x + y1.y * y1.y;
    __shared__ float sh[256];
    sh[tid] = ss;
    __syncthreads();
    for (int o = 128; o > 0; o >>= 1) {
        if (tid < o) sh[tid] += sh[tid + o];
        __syncthreads();
    }
    float scale = rsqrtf(sh[0] / DI + RMS_EPS);
    float4 wv = *reinterpret_cast<const float4*>(nw + tid * 4);
    __half2* yw = reinterpret_cast<__half2*>(yd) + tid * 2;
    yw[0] = __floats2half2_rn(y0.x * scale * wv.x, y0.y * scale * wv.y);
    yw[1] = __floats2half2_rn(y1.x * scale * wv.z, y1.y * scale * wv.w);
}

// ---------------- launch ----------------
extern "C" void kernel_launch(void* const* d_in, const int* in_sizes, int n_in,
                              void* d_out, int out_size) {
    (void)in_sizes; (void)n_in; (void)out_size;
    const float* x      = (const float*)d_in[0];
    const float* gn_w   = (const float*)d_in[1];
    const float* gn_b   = (const float*)d_in[2];
    const float* proj_w = (const float*)d_in[3];
    const float* proj_b = (const float*)d_in[4];
    const float* fw[8], *bw[8];
    for (int i = 0; i < 8; i++) { fw[i] = (const float*)d_in[5 + i]; bw[i] = (const float*)d_in[13 + i]; }
    float* out = (float*)d_out;

    float *t_, *dt_, *acs_, *st_, *pv_, *part_, *stats_;
    __half *th_, *zx_, *xbc_, *cb_, *yh_, *rh_, *wih_, *woh_, *wph_;
    cudaGetSymbolAddress((void**)&t_,    g_t);
    cudaGetSymbolAddress((void**)&th_,   g_th);
    cudaGetSymbolAddress((void**)&zx_,   g_zx);
    cudaGetSymbolAddress((void**)&xbc_,  g_xbc);
    cudaGetSymbolAddress((void**)&dt_,   g_dt);
    cudaGetSymbolAddress((void**)&acs_,  g_acs);
    cudaGetSymbolAddress((void**)&cb_,   g_cb);
    cudaGetSymbolAddress((void**)&st_,   g_st);
    cudaGetSymbolAddress((void**)&pv_,   g_pv);
    cudaGetSymbolAddress((void**)&yh_,   g_yh);
    cudaGetSymbolAddress((void**)&rh_,   g_rh);
    cudaGetSymbolAddress((void**)&wih_,  g_wih);
    cudaGetSymbolAddress((void**)&woh_,  g_woh);
    cudaGetSymbolAddress((void**)&wph_,  g_wph);
    cudaGetSymbolAddress((void**)&part_, g_part);
    cudaGetSymbolAddress((void**)&stats_,g_stats);

    static bool attr_done = false;
    if (!attr_done) {
        cudaFuncSetAttribute(gemm_h<0,1>, cudaFuncAttributeMaxDynamicSharedMemorySize, H_SMEM_BIG);
        cudaFuncSetAttribute(gemm_h<0,0>, cudaFuncAttributeMaxDynamicSharedMemorySize, H_SMEM_SMALL);
        cudaFuncSetAttribute(gemm_h<1,0>, cudaFuncAttributeMaxDynamicSharedMemorySize, H_SMEM_SMALL);
        cudaFuncSetAttribute(gemm_h<2,0>, cudaFuncAttributeMaxDynamicSharedMemorySize, H_SMEM_SMALL);
        attr_done = true;
    }

    prep_k<<<CVT_BLOCKS + GNP_BLOCKS, 256>>>(fw[0], bw[0], fw[7], bw[7], proj_w,
                                             wih_, woh_, wph_, x, part_);
    gn_fin_k<<<B_, 64>>>(part_, stats_);
    gn_apply_k<<<dim3(L_ / 32, DM / 32, B_), dim3(32, 8)>>>(x, gn_w, gn_b, stats_, t_, th_);

    // in-projection (big tile)
    gemm_h<0,1><<<dim3((DIP + 127) / 128, (B_ * L_) / 128, 2), 256, H_SMEM_BIG>>>(
        th_, wih_, wih_ + (long long)DIP * DM, zx_, B_ * L_, DIP, DM, DM, DM, DIP,
        0, 0, 0, 1, 0, SZ_ZX, L_, nullptr, nullptr);

    convdt_k<<<CONV_BLOCKS + DTS_BLOCKS, 256>>>(
        zx_, fw[1], fw[2], bw[1], bw[2], fw[3], fw[4], bw[3], bw[4],
        xbc_, dt_, acs_);

    // CB = C @ B^T (small tile, 512 CTAs)
    gemm_h<0,0><<<dim3(CH / 64, CH / 64, 2 * B_ * NC), 256, H_SMEM_SMALL>>>(
        xbc_ + DI + DS, xbc_ + DI, xbc_ + SZ_XBC + DI, cb_, CH, CH, DS, CD, CD, CH,
        (long long)CH * CD, (long long)CH * CD, (long long)CH * CH,
        B_ * NC, SZ_XBC, SZ_CB, 0, nullptr, nullptr);

    states_mma_k<<<dim3(NH, NC, 2 * B_), 256>>>(xbc_, dt_, acs_, st_);
    chunkscan_k<<<(2 * B_ * NH * HD * DS) / 256, 256>>>(st_, acs_, pv_);
    ssd_y_mma_k<<<dim3(CH / 64, NH, 2 * B_ * NC), 256>>>(
        xbc_, dt_, acs_, cb_, pv_, fw[5], bw[5], yh_);
    gate_rms_k<<<2 * B_ * L_, 256>>>(yh_, zx_, fw[6], bw[6]);

    // out-projection (small tile, 512 CTAs)
    gemm_h<1,0><<<dim3(DM / 64, (B_ * L_) / 64, 2), 256, H_SMEM_SMALL>>>(
        yh_, woh_, woh_ + (long long)DM * DI, rh_, B_ * L_, DM, DI, DI, DI, DM,
        0, 0, 0, 1, SZ_Y, 0, 0, t_, nullptr);

    // final projection (small tile, 256 CTAs)
    gemm_h<2,0><<<dim3(DM / 64, (B_ * L_) / 64, 1), 256, H_SMEM_SMALL>>>(
        rh_, wph_, wph_, out, B_ * L_, DM, 2 * DM, 2 * DM, 2 * DM, DM,
        0, 0, 0, 1, 0, 0, 0, x, proj_b);
}

// round 17
// speedup vs baseline: 1.0288x; 1.0288x over previous
#include <cuda_runtime.h>
#include <cuda_bf16.h>
#include <cuda_fp16.h>
#include <math.h>
#include <stdint.h>

// ---------------- problem constants ----------------
static const int B_   = 2;
static const int L_   = 2048;
static const int DM   = 256;
static const int DS   = 128;
static const int DI   = 1024;
static const int NH   = 16;
static const int HD   = 64;
static const int CD   = 1280;
static const int DIP  = 2320;
static const int CH   = 256;
static const int NC   = 8;
#define GN_EPS 1.1920928955078125e-07f
#define RMS_EPS 1e-5f

#define SZ_ZX   ((long long)B_*L_*DIP)
#define SZ_XBC  ((long long)B_*L_*CD)
#define SZ_DT   ((long long)B_*L_*NH)
#define SZ_ACS  ((long long)B_*NH*L_)
#define SZ_CB   ((long long)B_*NC*CH*CH)
#define SZ_ST   ((long long)B_*NC*NH*HD*DS)
#define SZ_Y    ((long long)B_*L_*DI)

#define CVT_TOTAL (2*DIP*DM + 2*DM*DI + DM*2*DM)
#define CVT_BLOCKS ((CVT_TOTAL + 255) / 256)
#define GNP_BLOCKS (64 * B_)
#define CONV_BLOCKS ((int)((2LL * B_ * (L_/4) * (CD/4) + 255) / 256))
#define DTS_BLOCKS (2 * B_ * NH * NC)

// ---------------- scratch ----------------
__device__ float  g_t    [B_*L_*DM];
__device__ __half g_th   [B_*L_*DM];
__device__ __half g_zx   [2*B_*L_*DIP];
__device__ __half g_xbc  [2*B_*L_*CD];
__device__ float  g_dt   [2*B_*L_*NH];
__device__ float  g_acs  [2*B_*NH*L_];
__device__ __half g_cb   [2*B_*NC*CH*CH];
__device__ float  g_st   [2*B_*NC*NH*HD*DS];
__device__ float  g_pv   [2*B_*NC*NH*HD*DS];
__device__ __half g_yh   [2*B_*L_*DI];
__device__ __half g_rh   [B_*L_*2*DM];
__device__ __half g_wih  [2*DIP*DM];
__device__ __half g_woh  [2*DM*DI];
__device__ __half g_wph  [DM*2*DM];
__device__ float  g_part [B_*64*2];
__device__ float  g_stats[4];

__device__ __forceinline__ float siluf(float x) { return x / (1.f + __expf(-x)); }
__device__ __forceinline__ float softplusf(float x) { return x > 20.f ? x : log1pf(expf(x)); }

#define MMA_F16(acc, a, b) \
    asm volatile( \
        "mma.sync.aligned.m16n8k16.row.col.f32.f16.f16.f32 " \
        "{%0,%1,%2,%3},{%4,%5,%6,%7},{%8,%9},{%0,%1,%2,%3};" \
        : "+f"((acc)[0]), "+f"((acc)[1]), "+f"((acc)[2]), "+f"((acc)[3]) \
        : "r"((a)[0]), "r"((a)[1]), "r"((a)[2]), "r"((a)[3]), \
          "r"((b)[0]), "r"((b)[1]))

__device__ __forceinline__ void ldsm_x4(uint32_t& r0, uint32_t& r1, uint32_t& r2,
                                        uint32_t& r3, uint32_t addr) {
    asm volatile("ldmatrix.sync.aligned.m8n8.x4.shared.b16 {%0,%1,%2,%3}, [%4];"
                 : "=r"(r0), "=r"(r1), "=r"(r2), "=r"(r3) : "r"(addr));
}

__device__ __forceinline__ void cpa16(uint32_t dst, const void* src, bool valid) {
    int sz = valid ? 16 : 0;
    asm volatile("cp.async.cg.shared.global [%0], [%1], 16, %2;\n"
                 :: "r"(dst), "l"(src), "r"(sz));
}
#define CPA_COMMIT() asm volatile("cp.async.commit_group;\n" ::)
#define CPA_WAIT1()  asm volatile("cp.async.wait_group 1;\n" ::)

// ---------------- fused: weight conversion + GroupNorm partials -------------
__global__ void prep_k(const float* __restrict__ a0, const float* __restrict__ a1,
                       const float* __restrict__ a2, const float* __restrict__ a3,
                       const float* __restrict__ a4,
                       __half* __restrict__ w_in, __half* __restrict__ w_out,
                       __half* __restrict__ w_pj,
                       const float* __restrict__ x, float* __restrict__ part) {
    int bi = blockIdx.x;
    if (bi < CVT_BLOCKS) {
        const int N1 = DIP * DM, N2 = DM * DI, N3 = DM * 2 * DM;
        int i = bi * 256 + threadIdx.x;
        if (i < N1) w_in[i] = __float2half(a0[i]);
        else if (i < 2 * N1) w_in[i] = __float2half(a1[i - N1]);
        else {
            int j = i - 2 * N1;
            if (j < N2) w_out[j] = __float2half(a2[j]);
            else if (j < 2 * N2) w_out[j] = __float2half(a3[j - N2]);
            else { int k = j - 2 * N2; if (k < N3) w_pj[k] = __float2half(a4[k]); }
        }
        return;
    }
    int gi = bi - CVT_BLOCKS;
    int b = gi / 64, blk = gi % 64;
    const float* xb = x + (size_t)b * DM * L_;
    float s = 0.f, ss = 0.f;
    for (int i = blk * 256 + threadIdx.x; i < DM * L_; i += 64 * 256) {
        float v = xb[i]; s += v; ss += v * v;
    }
    __shared__ float sh[256], sh2[256];
    sh[threadIdx.x] = s; sh2[threadIdx.x] = ss;
    __syncthreads();
    for (int o = 128; o > 0; o >>= 1) {
        if ((int)threadIdx.x < o) { sh[threadIdx.x] += sh[threadIdx.x + o]; sh2[threadIdx.x] += sh2[threadIdx.x + o]; }
        __syncthreads();
    }
    if (threadIdx.x == 0) {
        part[(b * 64 + blk) * 2 + 0] = sh[0];
        part[(b * 64 + blk) * 2 + 1] = sh2[0];
    }
}

__global__ void gn_fin_k(const float* __restrict__ part, float* __restrict__ stats) {
    int b = blockIdx.x;
    __shared__ double sh[64], sh2[64];
    int i = threadIdx.x;
    sh[i]  = (double)part[(b * 64 + i) * 2 + 0];
    sh2[i] = (double)part[(b * 64 + i) * 2 + 1];
    __syncthreads();
    for (int o = 32; o > 0; o >>= 1) {
        if (i < o) { sh[i] += sh[i + o]; sh2[i] += sh2[i + o]; }
        __syncthreads();
    }
    if (i == 0) {
        double n = (double)DM * L_;
        double mu = sh[0] / n;
        double var = sh2[0] / n - mu * mu;
        stats[b * 2 + 0] = (float)mu;
        stats[b * 2 + 1] = rsqrtf((float)var + GN_EPS);
    }
}

// ---------------- GroupNorm apply + transpose ----------------
__global__ void gn_apply_k(const float* __restrict__ x, const float* __restrict__ gw,
                           const float* __restrict__ gb, const float* __restrict__ stats,
                           float* __restrict__ t, __half* __restrict__ th) {
    int b = blockIdx.z;
    __shared__ float tile[32][33];
    int l0 = blockIdx.x * 32, d0 = blockIdx.y * 32;
    float mu = stats[b * 2], rs = stats[b * 2 + 1];
#pragma unroll
    for (int r = 0; r < 4; r++) {
        int d = d0 + threadIdx.y + r * 8;
        tile[threadIdx.y + r * 8][threadIdx.x] = x[((size_t)b * DM + d) * L_ + l0 + threadIdx.x];
    }
    __syncthreads();
    int d = d0 + threadIdx.x;
    float w = gw[d], bb = gb[d];
#pragma unroll
    for (int r = 0; r < 4; r++) {
        int l = l0 + threadIdx.y + r * 8;
        float v = (tile[threadIdx.x][threadIdx.y + r * 8] - mu) * rs * w + bb;
        t[((size_t)b * L_ + l) * DM + d] = v;
        th[((size_t)b * L_ + l) * DM + d] = __float2half(v);
    }
}

// ---- FP16 NT GEMM, two tile configs, ldmatrix fragment loads ---------------
#define HBK 64
#define GST 3
#define GLDH2 72
#define H_SMEM_BIG   (GST * 256 * GLDH2 * 2)
#define H_SMEM_SMALL (GST * 128 * GLDH2 * 2)

template<int MODE, int TB>
__global__ void __launch_bounds__(256, (TB ? 2 : 3))
gemm_h(const __half* __restrict__ A, const __half* __restrict__ B0,
       const __half* __restrict__ B1, void* __restrict__ Cv,
       int M, int N, int K, int lda, int ldb, int ldc,
       long long sA, long long sB, long long sC,
       int zPerDir, long long dA, long long dC, int revL,
       const float* __restrict__ extra, const float* __restrict__ bias) {
    constexpr int T   = 256;
    constexpr int BMx = TB ? 128 : 64;
    constexpr int BNx = TB ? 128 : 64;
    constexpr int MF  = 2;
    constexpr int NF  = TB ? 8 : 2;
    constexpr int WTN = NF * 8;
    constexpr int WNW = BNx / WTN;
    constexpr int LA  = BMx * HBK / (T * 8);
    constexpr int LB  = BNx * HBK / (T * 8);
    extern __shared__ __half hsm[];
    __half* Asm = hsm;
    __half* Bsm = hsm + GST * BMx * GLDH2;
    int z = blockIdx.z;
    int dir = z / zPerDir, zz = z % zPerDir;
    const __half* Ap = A + dir * dA + zz * sA;
    const __half* Bp = (dir ? B1 : B0) + zz * sB;
    long long coff = dir * dC + zz * sC;
    int rev = dir ? revL : 0;
    int m0 = blockIdx.y * BMx, n0 = blockIdx.x * BNx;
    int tid = threadIdx.x;
    int warp = tid >> 5, lane = tid & 31;
    int wm = warp / WNW, wn = warp % WNW;
    int group = lane >> 2, tig = lane & 3;
    float acc[MF][NF][4] = {};

    // ldmatrix lane-address components
    int r8 = lane & 7;
    int aRow0 = wm * 32 + r8 + ((lane >> 3) & 1) * 8;   // + mf*16
    int aColO = ((lane >> 4) & 1) * 8;
    int bRow0 = wn * WTN + r8 + ((lane >> 4) & 1) * 8;  // + nfp*16
    int bColO = ((lane >> 3) & 1) * 8;

    auto issue = [&](int k0, int s) {
        __half* As = Asm + s * BMx * GLDH2;
        __half* Bs = Bsm + s * BNx * GLDH2;
#pragma unroll
        for (int i = 0; i < LA; i++) {
            int e = tid + i * T;
            int mm = e >> 3;
            int kc = (e & 7) * 8;
            int gm = m0 + mm;
            int row = gm < M ? gm : 0;
            if (rev && gm < M) { int bb = gm / rev; int ll = gm % rev; row = bb * rev + (rev - 1 - ll); }
            cpa16((uint32_t)__cvta_generic_to_shared(As + mm * GLDH2 + kc),
                  Ap + (long long)row * lda + k0 + kc, gm < M);
        }
#pragma unroll
        for (int i = 0; i < LB; i++) {
            int e = tid + i * T;
            int nn = e >> 3;
            int kc = (e & 7) * 8;
            int gn = n0 + nn;
            int rowb = gn < N ? gn : 0;
            cpa16((uint32_t)__cvta_generic_to_shared(Bs + nn * GLDH2 + kc),
                  Bp + (long long)rowb * ldb + k0 + kc, gn < N);
        }
    };
    auto compute = [&](int s) {
        uint32_t aBase = (uint32_t)__cvta_generic_to_shared(Asm + s * BMx * GLDH2);
        uint32_t bBase = (uint32_t)__cvta_generic_to_shared(Bsm + s * BNx * GLDH2);
#pragma unroll
        for (int ks = 0; ks < 4; ks++) {
            int kb = ks * 16;
            uint32_t af[MF][4], bf[NF][2];
#pragma unroll
            for (int mf = 0; mf < MF; mf++) {
                uint32_t addr = aBase + (uint32_t)(((aRow0 + mf * 16) * GLDH2 + kb + aColO) * 2);
                ldsm_x4(af[mf][0], af[mf][1], af[mf][2], af[mf][3], addr);
            }
#pragma unroll
            for (int nfp = 0; nfp < NF / 2; nfp++) {
                uint32_t addr = bBase + (uint32_t)(((bRow0 + nfp * 16) * GLDH2 + kb + bColO) * 2);
                ldsm_x4(bf[2*nfp][0], bf[2*nfp][1], bf[2*nfp+1][0], bf[2*nfp+1][1], addr);
            }
#pragma unroll
            for (int mf = 0; mf < MF; mf++)
#pragma unroll
                for (int nf = 0; nf < NF; nf++) MMA_F16(acc[mf][nf], af[mf], bf[nf]);
        }
    };

    int nIter = K / HBK;
    issue(0, 0);
    CPA_COMMIT();
    if (nIter > 1) issue(HBK, 1);
    CPA_COMMIT();
    for (int it = 0; it < nIter; it++) {
        CPA_WAIT1();
        __syncthreads();
        if (it + 2 < nIter) issue((it + 2) * HBK, (it + 2) % GST);
        CPA_COMMIT();
        compute(it % GST);
    }

#pragma unroll
    for (int mf = 0; mf < MF; mf++) {
#pragma unroll
        for (int nf = 0; nf < NF; nf++) {
            int gn = n0 + wn * WTN + nf * 8 + 2 * tig;
#pragma unroll
            for (int rr = 0; rr < 2; rr++) {
                int gm = m0 + wm * 32 + mf * 16 + group + rr * 8;
                float a0 = acc[mf][nf][rr * 2 + 0], a1 = acc[mf][nf][rr * 2 + 1];
                if (MODE == 0) {
                    if (gm < M && gn < N) {
                        __half2* cp2 = reinterpret_cast<__half2*>(Cv);
                        cp2[(coff + (long long)gm * ldc + gn) >> 1] = __floats2half2_rn(a0, a1);
                    }
                } else if (MODE == 1) {
                    int b = gm / L_, l = gm % L_;
                    int ltm = dir ? (L_ - 1 - l) : l;
                    long long base = (long long)(b * L_ + ltm);
                    float2 tv = *reinterpret_cast<const float2*>(extra + base * DM + gn);
                    __half2* rp = reinterpret_cast<__half2*>(Cv);
                    rp[(base * (2 * DM) + dir * DM + gn) >> 1] =
                        __floats2half2_rn(a0 + tv.x, a1 + tv.y);
                } else {
                    int b = gm / L_, l = gm % L_;
                    float* C = reinterpret_cast<float*>(Cv);
                    long long i0 = ((long long)(b * DM + gn)) * L_ + l;
                    long long i1 = ((long long)(b * DM + gn + 1)) * L_ + l;
                    C[i0] = extra[i0] + bias[gn] + a0;
                    C[i1] = extra[i1] + bias[gn + 1] + a1;
                }
            }
        }
    }
}

// ---------------- fused: depthwise conv+SiLU  AND  dt softplus+scan ---------
__global__ void convdt_k(const __half* __restrict__ zx,
                         const float* __restrict__ cw0, const float* __restrict__ cb0,
                         const float* __restrict__ cw1, const float* __restrict__ cb1,
                         const float* __restrict__ db0, const float* __restrict__ al0,
                         const float* __restrict__ db1, const float* __restrict__ al1,
                         __half* __restrict__ xbc,
                         float* __restrict__ dt, float* __restrict__ acs) {
    int bi = blockIdx.x;
    if (bi < CONV_BLOCKS) {
        long long idx = (long long)bi * 256 + threadIdx.x;
        if (idx >= 2LL * B_ * (L_ / 4) * (CD / 4)) return;
        int cg = idx % (CD / 4);
        int lb = (idx / (CD / 4)) % (L_ / 4);
        long long rest = idx / ((long long)(CD / 4) * (L_ / 4));
        int b = rest % B_;
        int dir = rest / B_;
        int l0 = lb * 4;
        const float* cw = (dir ? cw1 : cw0) + cg * 16;
        const float* cb = (dir ? cb1 : cb0) + cg * 4;
        const __half* zxd = zx + dir * SZ_ZX + (size_t)(b * L_) * DIP + DI + cg * 4;
        float4 w0 = *reinterpret_cast<const float4*>(cw);
        float4 w1 = *reinterpret_cast<const float4*>(cw + 4);
        float4 w2 = *reinterpret_cast<const float4*>(cw + 8);
        float4 w3 = *reinterpret_cast<const float4*>(cw + 12);
        float4 bv = *reinterpret_cast<const float4*>(cb);
        float4 v[7];
#pragma unroll
        for (int r = 0; r < 7; r++) {
            int lp = l0 - 3 + r;
            if (lp >= 0) {
                const __half2* p = reinterpret_cast<const __half2*>(zxd + (size_t)lp * DIP);
                float2 f0 = __half22float2(p[0]);
                float2 f1 = __half22float2(p[1]);
                v[r] = make_float4(f0.x, f0.y, f1.x, f1.y);
            } else v[r] = make_float4(0.f, 0.f, 0.f, 0.f);
        }
        __half* outp = xbc + dir * SZ_XBC + ((size_t)(b * L_ + l0)) * CD + cg * 4;
#pragma unroll
        for (int j = 0; j < 4; j++) {
            float4 acc = bv;
#pragma unroll
            for (int k = 0; k < 4; k++) {
                float4 f = v[j + k];
                acc.x += ((const float*)&w0)[k] * f.x;
                acc.y += ((const float*)&w1)[k] * f.y;
                acc.z += ((const float*)&w2)[k] * f.z;
                acc.w += ((const float*)&w3)[k] * f.w;
            }
            __half2* op = reinterpret_cast<__half2*>(outp + (size_t)j * CD);
            op[0] = __floats2half2_rn(siluf(acc.x), siluf(acc.y));
            op[1] = __floats2half2_rn(siluf(acc.z), siluf(acc.w));
        }
        return;
    }
    int di = bi - CONV_BLOCKS;
    int dir = di / (B_ * NH * NC);
    di %= B_ * NH * NC;
    int c = di % NC, h = (di / NC) % NH, b = di / (NC * NH);
    const float* dt_bias = dir ? db1 : db0;
    const float* A_log   = dir ? al1 : al0;
    int l = threadIdx.x;
    int lane = l & 31, warp = l >> 5;
    int gl = c * CH + l;
    int row = b * L_ + gl;
    float v = __half2float(zx[dir * SZ_ZX + (size_t)row * DIP + (DIP - NH) + h]) + dt_bias[h];
    float dtv = softplusf(v);
    dt[dir * SZ_DT + (size_t)row * NH + h] = dtv;
    float a = -expf(A_log[h]) * dtv;
#pragma unroll
    for (int o = 1; o < 32; o <<= 1) {
        float t = __shfl_up_sync(0xffffffff, a, o);
        if (lane >= o) a += t;
    }
    __shared__ float wsum[8];
    if (lane == 31) wsum[warp] = a;
    __syncthreads();
    float off = 0.f;
#pragma unroll
    for (int w = 0; w < 8; w++) if (w < warp) off += wsum[w];
    acs[dir * SZ_ACS + (size_t)(b * NH + h) * L_ + gl] = a + off;
}

// ---------------- per-chunk end state via fp16 mma ----------------
#define SLDH 40
__global__ void __launch_bounds__(256)
states_mma_k(const __half* __restrict__ xbc, const float* __restrict__ dt,
             const float* __restrict__ acs, float* __restrict__ st) {
    int h = blockIdx.x, c = blockIdx.y;
    int dir = blockIdx.z / B_, b = blockIdx.z % B_;
    const __half* xbcd = xbc + dir * SZ_XBC;
    const float* dtd  = dt  + dir * SZ_DT;
    const float* acsd = acs + dir * SZ_ACS;
    int tid = threadIdx.x;
    int warp = tid >> 5, lane = tid & 31;
    int wm = warp >> 2, wn = warp & 3;
    int group = lane >> 2, tig = lane & 3;
    __shared__ __half Xs[64][SLDH];
    __shared__ __half Bs[128][SLDH];
    __shared__ float wrow[CH];
    int acsbase = (b * NH + h) * L_ + c * CH;
    float csLast = acsd[acsbase + CH - 1];
    {
        int row = b * L_ + c * CH + tid;
        wrow[tid] = dtd[(size_t)row * NH + h] * __expf(csLast - acsd[acsbase + tid]);
    }
    __syncthreads();
    float acc[2][4][4] = {};
    for (int s0 = 0; s0 < CH; s0 += 32) {
#pragma unroll
        for (int i = 0; i < 8; i++) {
            int e = tid + i * 256;
            int pp = e & 63, ss = e >> 6;
            int row = b * L_ + c * CH + s0 + ss;
            Xs[pp][ss] = __float2half(
                __half2float(xbcd[(size_t)row * CD + h * HD + pp]) * wrow[s0 + ss]);
        }
#pragma unroll
        for (int i = 0; i < 16; i++) {
            int e = tid + i * 256;
            int nn = e & 127, ss = e >> 7;
            int row = b * L_ + c * CH + s0 + ss;
            Bs[nn][ss] = xbcd[(size_t)row * CD + DI + nn];
        }
        __syncthreads();
        const __half2* Xs2 = reinterpret_cast<const __half2*>(&Xs[0][0]);
        const __half2* Bs2 = reinterpret_cast<const __half2*>(&Bs[0][0]);
#pragma unroll
        for (int ks = 0; ks < 2; ks++) {
            int k2 = ks * 8;
            uint32_t af[2][4], bf[4][2];
#pragma unroll
            for (int mf = 0; mf < 2; mf++) {
                int rm = wm * 32 + mf * 16 + group;
                af[mf][0] = *reinterpret_cast<const uint32_t*>(&Xs2[(rm    ) * 20 + k2 + tig]);
                af[mf][1] = *reinterpret_cast<const uint32_t*>(&Xs2[(rm + 8) * 20 + k2 + tig]);
                af[mf][2] = *reinterpret_cast<const uint32_t*>(&Xs2[(rm    ) * 20 + k2 + tig + 4]);
                af[mf][3] = *reinterpret_cast<const uint32_t*>(&Xs2[(rm + 8) * 20 + k2 + tig + 4]);
            }
#pragma unroll
            for (int nf = 0; nf < 4; nf++) {
                int rn = wn * 32 + nf * 8 + group;
                bf[nf][0] = *reinterpret_cast<const uint32_t*>(&Bs2[rn * 20 + k2 + tig]);
                bf[nf][1] = *reinterpret_cast<const uint32_t*>(&Bs2[rn * 20 + k2 + tig + 4]);
            }
#pragma unroll
            for (int mf = 0; mf < 2; mf++)
#pragma unroll
                for (int nf = 0; nf < 4; nf++) MMA_F16(acc[mf][nf], af[mf], bf[nf]);
        }
        __syncthreads();
    }
    float* base = st + dir * SZ_ST + (size_t)((b * NC + c) * NH + h) * HD * DS;
#pragma unroll
    for (int mf = 0; mf < 2; mf++) {
#pragma unroll
        for (int nf = 0; nf < 4; nf++) {
            int gm = wm * 32 + mf * 16 + group;
            int gn = wn * 32 + nf * 8 + 2 * tig;
            *reinterpret_cast<float2*>(base + gm * DS + gn) =
                make_float2(acc[mf][nf][0], acc[mf][nf][1]);
            *reinterpret_cast<float2*>(base + (gm + 8) * DS + gn) =
                make_float2(acc[mf][nf][2], acc[mf][nf][3]);
        }
    }
}

// ---------------- inter-chunk recurrence ----------------
__global__ void chunkscan_k(const float* __restrict__ st, const float* __restrict__ acs,
                            float* __restrict__ pv) {
    int idx = blockIdx.x * blockDim.x + threadIdx.x;
    int n = idx & (DS - 1);
    int p = (idx >> 7) & (HD - 1);
    int h = (idx >> 13) & (NH - 1);
    int b = (idx >> 17) & (B_ - 1);
    int dir = idx >> 18;
    const float* std_ = st + dir * SZ_ST;
    const float* acsd = acs + dir * SZ_ACS;
    float* pvd = pv + dir * SZ_ST;
    float S = 0.f;
    for (int c = 0; c < NC; c++) {
        size_t off = ((size_t)((b * NC + c) * NH + h) * HD + p) * DS + n;
        pvd[off] = S;
        float at = acsd[(b * NH + h) * L_ + c * CH + CH - 1];
        S = S * expf(at) + std_[off];
    }
}

// ---------------- Y via fp16 mma -> fp16 output ----------------
__global__ void __launch_bounds__(256)
ssd_y_mma_k(const __half* __restrict__ xbc, const float* __restrict__ dt,
            const float* __restrict__ acs, const __half* __restrict__ cb,
            const float* __restrict__ pv,
            const float* __restrict__ Dh0, const float* __restrict__ Dh1,
            __half* __restrict__ yh) {
    int lt = blockIdx.x, h = blockIdx.y;
    int dir = blockIdx.z / (B_ * NC);
    int bc = blockIdx.z % (B_ * NC);
    int c = bc % NC, b = bc / NC;
    const __half* xbcd = xbc + dir * SZ_XBC;
    const float* dtd  = dt  + dir * SZ_DT;
    const float* acsd = acs + dir * SZ_ACS;
    const float* Dh   = dir ? Dh1 : Dh0;
    int tid = threadIdx.x;
    int warp = tid >> 5, lane = tid & 31;
    int wm = warp >> 2, wn = warp & 3;
    int group = lane >> 2, tig = lane & 3;
    __shared__ __half Ws[64][SLDH];
    __shared__ __half Xs[64][SLDH];
    __shared__ __half Ps[64][SLDH];
    __shared__ float csl[64], el64[64], eoff[64];
    __shared__ float einv[CH];
    int l0 = lt * 64;
    int acsbase = (b * NH + h) * L_ + c * CH;
    float csl0 = acsd[acsbase + l0];
    if (tid < 64) {
        float v = acsd[acsbase + l0 + tid];
        csl[tid]  = v;
        el64[tid] = __expf(v - csl0);
        eoff[tid] = __expf(v);
    }
    einv[tid] = __expf(csl0 - acsd[acsbase + tid]);
    __syncthreads();
    const __half* cbb = cb + dir * SZ_CB + (size_t)(b * NC + c) * CH * CH;
    float acc[2][2][4] = {};
    int nst = 2 * lt + 2;
    for (int stp = 0; stp < nst; stp++) {
        int s0 = stp * 32;
        bool lower = (s0 + 31 < l0);
        if (lower) {
#pragma unroll
            for (int i = 0; i < 8; i++) {
                int e = tid + i * 256;
                int j = e & 31, ii = e >> 5;
                Ws[ii][j] = __float2half(el64[ii] * einv[s0 + j] *
                                         __half2float(cbb[(l0 + ii) * CH + s0 + j]));
            }
        } else {
#pragma unroll
            for (int i = 0; i < 8; i++) {
                int e = tid + i * 256;
                int j = e & 31, ii = e >> 5;
                float w = 0.f;
                if (s0 + j <= l0 + ii)
                    w = __expf(csl[ii] - acsd[acsbase + s0 + j]) *
                        __half2float(cbb[(l0 + ii) * CH + s0 + j]);
                Ws[ii][j] = __float2half(w);
            }
        }
#pragma unroll
        for (int i = 0; i < 8; i++) {
            int e = tid + i * 256;
            int pp = e & 63, ss = e >> 6;
            int row = b * L_ + c * CH + s0 + ss;
            Xs[pp][ss] = __float2half(
                __half2float(xbcd[(size_t)row * CD + h * HD + pp]) * dtd[(size_t)row * NH + h]);
        }
        __syncthreads();
        const __half2* Ws2 = reinterpret_cast<const __half2*>(&Ws[0][0]);
        const __half2* Xs2 = reinterpret_cast<const __half2*>(&Xs[0][0]);
#pragma unroll
        for (int ks = 0; ks < 2; ks++) {
            int k2 = ks * 8;
            uint32_t af[2][4], bf[2][2];
#pragma unroll
            for (int mf = 0; mf < 2; mf++) {
                int rm = wm * 32 + mf * 16 + group;
                af[mf][0] = *reinterpret_cast<const uint32_t*>(&Ws2[(rm    ) * 20 + k2 + tig]);
                af[mf][1] = *reinterpret_cast<const uint32_t*>(&Ws2[(rm + 8) * 20 + k2 + tig]);
                af[mf][2] = *reinterpret_cast<const uint32_t*>(&Ws2[(rm    ) * 20 + k2 + tig + 4]);
                af[mf][3] = *reinterpret_cast<const uint32_t*>(&Ws2[(rm + 8) * 20 + k2 + tig + 4]);
            }
#pragma unroll
            for (int nf = 0; nf < 2; nf++) {
                int rn = wn * 16 + nf * 8 + group;
                bf[nf][0] = *reinterpret_cast<const uint32_t*>(&Xs2[rn * 20 + k2 + tig]);
                bf[nf][1] = *reinterpret_cast<const uint32_t*>(&Xs2[rn * 20 + k2 + tig + 4]);
            }
#pragma unroll
            for (int mf = 0; mf < 2; mf++)
#pragma unroll
                for (int nf = 0; nf < 2; nf++) MMA_F16(acc[mf][nf], af[mf], bf[nf]);
        }
        __syncthreads();
    }
    const float* pvb = pv + dir * SZ_ST + (size_t)((b * NC + c) * NH + h) * HD * DS;
    for (int nt = 0; nt < 4; nt++) {
        int n0 = nt * 32;
#pragma unroll
        for (int i = 0; i < 8; i++) {
            int e = tid + i * 256;
            int j = e & 31, ii = e >> 5;
            int row = b * L_ + c * CH + l0 + ii;
            Ws[ii][j] = __float2half(
                __half2float(xbcd[(size_t)row * CD + DI + DS + n0 + j]) * eoff[ii]);
        }
#pragma unroll
        for (int i = 0; i < 8; i++) {
            int e = tid + i * 256;
            int j = e & 31, pp = e >> 5;
            Ps[pp][j] = __float2half(pvb[pp * DS + n0 + j]);
        }
        __syncthreads();
        const __half2* Ws2 = reinterpret_cast<const __half2*>(&Ws[0][0]);
        const __half2* Ps2 = reinterpret_cast<const __half2*>(&Ps[0][0]);
#pragma unroll
        for (int ks = 0; ks < 2; ks++) {
            int k2 = ks * 8;
            uint32_t af[2][4], bf[2][2];
#pragma unroll
            for (int mf = 0; mf < 2; mf++) {
                int rm = wm * 32 + mf * 16 + group;
                af[mf][0] = *reinterpret_cast<const uint32_t*>(&Ws2[(rm    ) * 20 + k2 + tig]);
                af[mf][1] = *reinterpret_cast<const uint32_t*>(&Ws2[(rm + 8) * 20 + k2 + tig]);
                af[mf][2] = *reinterpret_cast<const uint32_t*>(&Ws2[(rm    ) * 20 + k2 + tig + 4]);
                af[mf][3] = *reinterpret_cast<const uint32_t*>(&Ws2[(rm + 8) * 20 + k2 + tig + 4]);
            }
#pragma unroll
            for (int nf = 0; nf < 2; nf++) {
                int rn = wn * 16 + nf * 8 + group;
                bf[nf][0] = *reinterpret_cast<const uint32_t*>(&Ps2[rn * 20 + k2 + tig]);
                bf[nf][1] = *reinterpret_cast<const uint32_t*>(&Ps2[rn * 20 + k2 + tig + 4]);
            }
#pragma unroll
            for (int mf = 0; mf < 2; mf++)
#pragma unroll
                for (int nf = 0; nf < 2; nf++) MMA_F16(acc[mf][nf], af[mf], bf[nf]);
        }
        __syncthreads();
    }
    float dh = Dh[h];
    __half* yd = yh + dir * SZ_Y;
#pragma unroll
    for (int mf = 0; mf < 2; mf++) {
#pragma unroll
        for (int nf = 0; nf < 2; nf++) {
            int ll = l0 + wm * 32 + mf * 16 + group;
            int pp = wn * 16 + nf * 8 + 2 * tig;
#pragma unroll
            for (int rr = 0; rr < 2; rr++) {
                int row = b * L_ + c * CH + ll + rr * 8;
                __half2 xrh = *reinterpret_cast<const __half2*>(
                    xbcd + (size_t)row * CD + h * HD + pp);
                float2 xr = __half22float2(xrh);
                *reinterpret_cast<__half2*>(yd + (size_t)row * DI + h * HD + pp) =
                    __floats2half2_rn(acc[mf][nf][rr * 2 + 0] + xr.x * dh,
                                      acc[mf][nf][rr * 2 + 1] + xr.y * dh);
            }
        }
    }
}

// ---------------- gating + RMSNorm, in place on fp16 yh ----------------
__global__ void gate_rms_k(__half* __restrict__ yh, const __half* __restrict__ zx,
                           const float* __restrict__ nw0, const float* __restrict__ nw1) {
    int row = blockIdx.x;
    int dir = row / (B_ * L_);
    row %= B_ * L_;
    const float* nw = dir ? nw1 : nw0;
    __half* yd = yh + dir * SZ_Y + (size_t)row * DI;
    const __half* zxd = zx + dir * SZ_ZX + (size_t)row * DIP;
    int tid = threadIdx.x;
    const __half2* yp = reinterpret_cast<const __half2*>(yd) + tid * 2;
    float2 y0 = __half22float2(yp[0]);
    float2 y1 = __half22float2(yp[1]);
    const __half2* zp = reinterpret_cast<const __half2*>(zxd + tid * 4);
    float2 z0 = __half22float2(zp[0]);
    float2 z1 = __half22float2(zp[1]);
    y0.x *= siluf(z0.x); y0.y *= siluf(z0.y); y1.x *= siluf(z1.x); y1.y *= siluf(z1.y);
    float ss = y0.x * y0.x + y0.y * y0.y + y1.x * y1.x + y1.y * y1.y;
    __shared__ float sh[256];
    sh[tid] = ss;
    __syncthreads();
    for (int o = 128; o > 0; o >>= 1) {
        if (tid < o) sh[tid] += sh[tid + o];
        __syncthreads();
    }
    float scale = rsqrtf(sh[0] / DI + RMS_EPS);
    float4 wv = *reinterpret_cast<const float4*>(nw + tid * 4);
    __half2* yw = reinterpret_cast<__half2*>(yd) + tid * 2;
    yw[0] = __floats2half2_rn(y0.x * scale * wv.x, y0.y * scale * wv.y);
    yw[1] = __floats2half2_rn(y1.x * scale * wv.z, y1.y * scale * wv.w);
}

// ---------------- launch ----------------
extern "C" void kernel_launch(void* const* d_in, const int* in_sizes, int n_in,
                              void* d_out, int out_size) {
    (void)in_sizes; (void)n_in; (void)out_size;
    const float* x      = (const float*)d_in[0];
    const float* gn_w   = (const float*)d_in[1];
    const float* gn_b   = (const float*)d_in[2];
    const float* proj_w = (const float*)d_in[3];
    const float* proj_b = (const float*)d_in[4];
    const float* fw[8], *bw[8];
    for (int i = 0; i < 8; i++) { fw[i] = (const float*)d_in[5 + i]; bw[i] = (const float*)d_in[13 + i]; }
    float* out = (float*)d_out;

    float *t_, *dt_, *acs_, *st_, *pv_, *part_, *stats_;
    __half *th_, *zx_, *xbc_, *cb_, *yh_, *rh_, *wih_, *woh_, *wph_;
    cudaGetSymbolAddress((void**)&t_,    g_t);
    cudaGetSymbolAddress((void**)&th_,   g_th);
    cudaGetSymbolAddress((void**)&zx_,   g_zx);
    cudaGetSymbolAddress((void**)&xbc_,  g_xbc);
    cudaGetSymbolAddress((void**)&dt_,   g_dt);
    cudaGetSymbolAddress((void**)&acs_,  g_acs);
    cudaGetSymbolAddress((void**)&cb_,   g_cb);
    cudaGetSymbolAddress((void**)&st_,   g_st);
    cudaGetSymbolAddress((void**)&pv_,   g_pv);
    cudaGetSymbolAddress((void**)&yh_,   g_yh);
    cudaGetSymbolAddress((void**)&rh_,   g_rh);
    cudaGetSymbolAddress((void**)&wih_,  g_wih);
    cudaGetSymbolAddress((void**)&woh_,  g_woh);
    cudaGetSymbolAddress((void**)&wph_,  g_wph);
    cudaGetSymbolAddress((void**)&part_, g_part);
    cudaGetSymbolAddress((void**)&stats_,g_stats);

    static bool attr_done = false;
    if (!attr_done) {
        cudaFuncSetAttribute(gemm_h<0,1>, cudaFuncAttributeMaxDynamicSharedMemorySize, H_SMEM_BIG);
        cudaFuncSetAttribute(gemm_h<0,0>, cudaFuncAttributeMaxDynamicSharedMemorySize, H_SMEM_SMALL);
        cudaFuncSetAttribute(gemm_h<1,0>, cudaFuncAttributeMaxDynamicSharedMemorySize, H_SMEM_SMALL);
        cudaFuncSetAttribute(gemm_h<2,0>, cudaFuncAttributeMaxDynamicSharedMemorySize, H_SMEM_SMALL);
        attr_done = true;
    }

    prep_k<<<CVT_BLOCKS + GNP_BLOCKS, 256>>>(fw[0], bw[0], fw[7], bw[7], proj_w,
                                             wih_, woh_, wph_, x, part_);
    gn_fin_k<<<B_, 64>>>(part_, stats_);
    gn_apply_k<<<dim3(L_ / 32, DM / 32, B_), dim3(32, 8)>>>(x, gn_w, gn_b, stats_, t_, th_);

    gemm_h<0,1><<<dim3((DIP + 127) / 128, (B_ * L_) / 128, 2), 256, H_SMEM_BIG>>>(
        th_, wih_, wih_ + (long long)DIP * DM, zx_, B_ * L_, DIP, DM, DM, DM, DIP,
        0, 0, 0, 1, 0, SZ_ZX, L_, nullptr, nullptr);

    convdt_k<<<CONV_BLOCKS + DTS_BLOCKS, 256>>>(
        zx_, fw[1], fw[2], bw[1], bw[2], fw[3], fw[4], bw[3], bw[4],
        xbc_, dt_, acs_);

    gemm_h<0,0><<<dim3(CH / 64, CH / 64, 2 * B_ * NC), 256, H_SMEM_SMALL>>>(
        xbc_ + DI + DS, xbc_ + DI, xbc_ + SZ_XBC + DI, cb_, CH, CH, DS, CD, CD, CH,
        (long long)CH * CD, (long long)CH * CD, (long long)CH * CH,
        B_ * NC, SZ_XBC, SZ_CB, 0, nullptr, nullptr);

    states_mma_k<<<dim3(NH, NC, 2 * B_), 256>>>(xbc_, dt_, acs_, st_);
    chunkscan_k<<<(2 * B_ * NH * HD * DS) / 256, 256>>>(st_, acs_, pv_);
    ssd_y_mma_k<<<dim3(CH / 64, NH, 2 * B_ * NC), 256>>>(
        xbc_, dt_, acs_, cb_, pv_, fw[5], bw[5], yh_);
    gate_rms_k<<<2 * B_ * L_, 256>>>(yh_, zx_, fw[6], bw[6]);

    gemm_h<1,0><<<dim3(DM / 64, (B_ * L_) / 64, 2), 256, H_SMEM_SMALL>>>(
        yh_, woh_, woh_ + (long long)DM * DI, rh_, B_ * L_, DM, DI, DI, DI, DM,
        0, 0, 0, 1, SZ_Y, 0, 0, t_, nullptr);

    gemm_h<2,0><<<dim3(DM / 64, (B_ * L_) / 64, 1), 256, H_SMEM_SMALL>>>(
        rh_, wph_, wph_, out, B_ * L_, DM, 2 * DM, 2 * DM, 2 * DM, DM,
        0, 0, 0, 1, 0, 0, 0, x, proj_b);
}